// round 12
// baseline (speedup 1.0000x reference)
#include <cuda_runtime.h>
#include <cuda_fp16.h>
#include <cstdint>

// ---------------- problem constants ----------------
#define S_    2048
#define N_    8
#define E_    512
#define C_    1024
#define G_    32
#define CG_   32
#define TOK_  (S_ * N_)          // 16384 tokens
#define LN_EPS 1e-5f

// GEMM tiling (mma.sync path — tcgen05 unavailable on this toolchain)
#define BM 128
#define BN 128
#define BK 32
#define NCHUNK1 32                // gemm1: 2 fp16 split segments x (512/32)
#define NCHUNK2 32                // gemm2: K=1024 / 32
#define ASTRIDE 40                // smem row stride in fp16 elems (80 B)

// refinement trigger: fp16-2seg logit error bound ~8e-4 max; 5x headroom
#define REFINE_THR 4e-3f

// ---------------- scratch (device globals) --------
__device__ __half g_Ahi[(size_t)TOK_ * E_];            // 16 MB
__device__ __half g_Alo[(size_t)TOK_ * E_];            // 16 MB
__device__ __half g_Bhi[(size_t)C_ * E_];              // 1 MB
__device__ __half g_sampH[(size_t)TOK_ * C_];          // 32 MB (fp16 sampled)
__device__ __half g_W2h[(size_t)E_ * C_];              // 1 MB  (fp16 W2, [e][c])
__device__ float  g_posPre[(size_t)TOK_ * E_];         // 32 MB (pre-LN projection)

// ---------------- helpers ----------------
__device__ __forceinline__ uint32_t smem_u32(const void* p) {
    uint32_t a;
    asm("{ .reg .u64 t; cvta.to.shared.u64 t, %1; cvt.u32.u64 %0, t; }"
        : "=r"(a) : "l"(p));
    return a;
}
__device__ __forceinline__ void cp16(uint32_t saddr, const void* gptr) {
    asm volatile("cp.async.cg.shared.global [%0], [%1], 16;"
                 :: "r"(saddr), "l"(gptr) : "memory");
}
__device__ __forceinline__ void ldm_x4(uint32_t* r, uint32_t addr) {
    asm volatile("ldmatrix.sync.aligned.m8n8.x4.shared.b16 {%0,%1,%2,%3}, [%4];"
                 : "=r"(r[0]), "=r"(r[1]), "=r"(r[2]), "=r"(r[3]) : "r"(addr));
}
__device__ __forceinline__ void mma16816(float* c, const uint32_t* a, const uint32_t* b) {
    asm volatile(
        "mma.sync.aligned.m16n8k16.row.col.f32.f16.f16.f32 "
        "{%0,%1,%2,%3}, {%4,%5,%6,%7}, {%8,%9}, {%0,%1,%2,%3};"
        : "+f"(c[0]), "+f"(c[1]), "+f"(c[2]), "+f"(c[3])
        : "r"(a[0]), "r"(a[1]), "r"(a[2]), "r"(a[3]), "r"(b[0]), "r"(b[1]));
}

// ---------------- kernel 0a: fp32 -> (fp16 hi, fp16 lo) split of x --------
__global__ void split_x_k(const float* __restrict__ in) {
    int i = blockIdx.x * 256 + threadIdx.x;
    if (i < TOK_ * E_ / 4) {
        float4 v = ((const float4*)in)[i];
        __half h0 = __float2half_rn(v.x), h1 = __float2half_rn(v.y);
        __half h2 = __float2half_rn(v.z), h3 = __float2half_rn(v.w);
        __half2 hi01, hi23, lo01, lo23;
        hi01.x = h0; hi01.y = h1; hi23.x = h2; hi23.y = h3;
        lo01.x = __float2half_rn(v.x - __half2float(h0));
        lo01.y = __float2half_rn(v.y - __half2float(h1));
        lo23.x = __float2half_rn(v.z - __half2float(h2));
        lo23.y = __float2half_rn(v.w - __half2float(h3));
        ((__half2*)g_Ahi)[i * 2]     = hi01;
        ((__half2*)g_Ahi)[i * 2 + 1] = hi23;
        ((__half2*)g_Alo)[i * 2]     = lo01;
        ((__half2*)g_Alo)[i * 2 + 1] = lo23;
    }
}
// ---------------- kernel 0b: W1 -> fp16 ------------------------------------
__global__ void split_w_k(const float* __restrict__ in) {
    int i = blockIdx.x * 256 + threadIdx.x;
    if (i < C_ * E_ / 4) {
        float4 v = ((const float4*)in)[i];
        __half2 hi01, hi23;
        hi01.x = __float2half_rn(v.x); hi01.y = __float2half_rn(v.y);
        hi23.x = __float2half_rn(v.z); hi23.y = __float2half_rn(v.w);
        ((__half2*)g_Bhi)[i * 2]     = hi01;
        ((__half2*)g_Bhi)[i * 2 + 1] = hi23;
    }
}
// ---------------- kernel 0c: W2 -> fp16 (layout kept: [e][c]) --------------
__global__ void w2h_k(const float* __restrict__ in) {
    int i = blockIdx.x * 256 + threadIdx.x;
    if (i < E_ * C_ / 4) {
        float4 v = ((const float4*)in)[i];
        __half2 h01, h23;
        h01.x = __float2half_rn(v.x); h01.y = __float2half_rn(v.y);
        h23.x = __float2half_rn(v.z); h23.y = __float2half_rn(v.w);
        ((__half2*)g_W2h)[i * 2]     = h01;
        ((__half2*)g_W2h)[i * 2 + 1] = h23;
    }
}

// ---------------- kernel 1: fp16 split-GEMM + fused softmax/sampling ------
// logits = 3(x.W1^T + b1) + coff computed in registers; per-group softmax,
// two Gumbel argmaxes, sampled outputs all emitted from the epilogue.
// Quad layout: lanes 4g..4g+3 jointly hold all 32 columns of each class
// group for their rows; reductions are quad-scope shfl (per-quad masks).
__global__ void __launch_bounds__(256, 2)
gemm_mma(const float* __restrict__ b1, const float* __restrict__ coff,
         const float* __restrict__ x,  const float* __restrict__ W1,
         const float* __restrict__ g1, const float* __restrict__ g2,
         const float* __restrict__ wI, const float* __restrict__ uI,
         float* __restrict__ oSamp, float* __restrict__ oSoft)
{
    __shared__ __align__(16) __half sA[2][BM * ASTRIDE];
    __shared__ __align__(16) __half sB[2][BN * ASTRIDE];

    const int tid  = threadIdx.x;
    const int lane = tid & 31;
    const int wid  = tid >> 5;
    const int wm   = (wid & 3) * 32;
    const int wn   = (wid >> 2) * 64;
    const int m0   = blockIdx.y * BM;
    const int n0   = blockIdx.x * BN;

    const uint32_t aBase[2] = { smem_u32(&sA[0][0]), smem_u32(&sA[1][0]) };
    const uint32_t bBase[2] = { smem_u32(&sB[0][0]), smem_u32(&sB[1][0]) };

    const int lrow0 = tid >> 2,         lcg0 = (tid & 3);
    const int lrow1 = (tid + 256) >> 2, lcg1 = ((tid + 256) & 3);

    auto issue_loads = [&](int kc) {
        const int b   = kc & 1;
        const int seg = kc >> 4;
        const __half* Asrc = seg ? g_Alo : g_Ahi;
        const int kcol = (kc & 15) * BK;
        cp16(aBase[b] + (uint32_t)(lrow0 * ASTRIDE + lcg0 * 8) * 2,
             Asrc + (size_t)(m0 + lrow0) * E_ + kcol + lcg0 * 8);
        cp16(aBase[b] + (uint32_t)(lrow1 * ASTRIDE + lcg1 * 8) * 2,
             Asrc + (size_t)(m0 + lrow1) * E_ + kcol + lcg1 * 8);
        cp16(bBase[b] + (uint32_t)(lrow0 * ASTRIDE + lcg0 * 8) * 2,
             g_Bhi + (size_t)(n0 + lrow0) * E_ + kcol + lcg0 * 8);
        cp16(bBase[b] + (uint32_t)(lrow1 * ASTRIDE + lcg1 * 8) * 2,
             g_Bhi + (size_t)(n0 + lrow1) * E_ + kcol + lcg1 * 8);
        asm volatile("cp.async.commit_group;" ::: "memory");
    };

    float acc[2][8][4];
    #pragma unroll
    for (int i = 0; i < 2; i++)
        #pragma unroll
        for (int j = 0; j < 8; j++)
            #pragma unroll
            for (int r = 0; r < 4; r++) acc[i][j][r] = 0.0f;

    issue_loads(0);

    for (int kc = 0; kc < NCHUNK1; kc++) {
        const int b = kc & 1;
        if (kc + 1 < NCHUNK1) {
            issue_loads(kc + 1);
            asm volatile("cp.async.wait_group 1;" ::: "memory");
        } else {
            asm volatile("cp.async.wait_group 0;" ::: "memory");
        }
        __syncthreads();

        #pragma unroll
        for (int ks = 0; ks < 2; ks++) {
            uint32_t afr[2][4];
            #pragma unroll
            for (int i = 0; i < 2; i++) {
                int row  = wm + i * 16 + (lane & 7) + ((lane >> 3) & 1) * 8;
                int half = lane >> 4;
                ldm_x4(afr[i], aBase[b] + row * (ASTRIDE * 2) + ks * 32 + half * 16);
            }
            uint32_t bfr[8][2];
            #pragma unroll
            for (int bj = 0; bj < 4; bj++) {
                int row  = wn + bj * 16 + (lane & 7) + (lane >> 4) * 8;
                int half = (lane >> 3) & 1;
                uint32_t q[4];
                ldm_x4(q, bBase[b] + row * (ASTRIDE * 2) + ks * 32 + half * 16);
                bfr[bj * 2][0] = q[0];     bfr[bj * 2][1] = q[1];
                bfr[bj * 2 + 1][0] = q[2]; bfr[bj * 2 + 1][1] = q[3];
            }
            #pragma unroll
            for (int i = 0; i < 2; i++)
                #pragma unroll
                for (int j = 0; j < 8; j++)
                    mma16816(acc[i][j], afr[i], bfr[j]);
        }
        __syncthreads();
    }

    // ---------------- fused epilogue: softmax + sampling ----------------
    const int gp   = lane >> 2;
    const int tid4 = lane & 3;
    const unsigned qmask = 0xFu << (lane & 28);   // this quad's 4 lanes

    #pragma unroll
    for (int i = 0; i < 2; i++)
    #pragma unroll
    for (int rr = 0; rr < 2; rr++) {
        const int row = m0 + wm + i * 16 + gp + rr * 8;
        const size_t rowC = (size_t)row * C_;
        #pragma unroll
        for (int h = 0; h < 2; h++) {
            const int gidx = (n0 + wn) / 32 + h;   // global group id
            const int nb   = n0 + wn + h * 32 + tid4 * 2;  // lane's first col

            // logits for this lane's 8 columns (cols nb+jj*8, nb+jj*8+1)
            float v[8];
            #pragma unroll
            for (int jj = 0; jj < 4; jj++) {
                int j = h * 4 + jj;
                int n = nb + jj * 8;
                float c0 = fmaf(3.0f, __ldg(&b1[n]),     __ldg(&coff[n]));
                float c1 = fmaf(3.0f, __ldg(&b1[n + 1]), __ldg(&coff[n + 1]));
                v[jj * 2]     = fmaf(3.0f, acc[i][j][rr * 2],     c0);
                v[jj * 2 + 1] = fmaf(3.0f, acc[i][j][rr * 2 + 1], c1);
            }

            // softmax (quad-scope reductions; exact max)
            float mx = v[0];
            #pragma unroll
            for (int k = 1; k < 8; k++) mx = fmaxf(mx, v[k]);
            mx = fmaxf(mx, __shfl_xor_sync(qmask, mx, 1));
            mx = fmaxf(mx, __shfl_xor_sync(qmask, mx, 2));
            float e[8], s = 0.f;
            #pragma unroll
            for (int k = 0; k < 8; k++) { e[k] = __expf(v[k] - mx); s += e[k]; }
            s += __shfl_xor_sync(qmask, s, 1);
            s += __shfl_xor_sync(qmask, s, 2);
            const float inv_s = 1.0f / s;

            // draw 1: argmax(v + g1) with margin
            float z[8];
            #pragma unroll
            for (int jj = 0; jj < 4; jj++) {
                float2 ga = __ldg((const float2*)&g1[rowC + nb + jj * 8]);
                z[jj * 2] = v[jj * 2] + ga.x; z[jj * 2 + 1] = v[jj * 2 + 1] + ga.y;
            }
            float bv1 = z[0]; int bi1 = nb;
            #pragma unroll
            for (int k = 1; k < 8; k++) {      // ascending col order: first wins ties
                int n = nb + (k >> 1) * 8 + (k & 1);
                if (z[k] > bv1) { bv1 = z[k]; bi1 = n; }
            }
            #pragma unroll
            for (int off = 1; off <= 2; off <<= 1) {
                float oz = __shfl_xor_sync(qmask, bv1, off);
                int   oi = __shfl_xor_sync(qmask, bi1, off);
                if (oz > bv1 || (oz == bv1 && oi < bi1)) { bv1 = oz; bi1 = oi; }
            }
            float sec = -3.4e38f;
            #pragma unroll
            for (int k = 0; k < 8; k++) {
                int n = nb + (k >> 1) * 8 + (k & 1);
                if (n != bi1) sec = fmaxf(sec, z[k]);
            }
            sec = fmaxf(sec, __shfl_xor_sync(qmask, sec, 1));
            sec = fmaxf(sec, __shfl_xor_sync(qmask, sec, 2));
            const float m1 = bv1 - sec;

            // draw 2
            #pragma unroll
            for (int jj = 0; jj < 4; jj++) {
                float2 gb = __ldg((const float2*)&g2[rowC + nb + jj * 8]);
                z[jj * 2] = v[jj * 2] + gb.x; z[jj * 2 + 1] = v[jj * 2 + 1] + gb.y;
            }
            float bv2 = z[0]; int bi2 = nb;
            #pragma unroll
            for (int k = 1; k < 8; k++) {
                int n = nb + (k >> 1) * 8 + (k & 1);
                if (z[k] > bv2) { bv2 = z[k]; bi2 = n; }
            }
            #pragma unroll
            for (int off = 1; off <= 2; off <<= 1) {
                float oz = __shfl_xor_sync(qmask, bv2, off);
                int   oi = __shfl_xor_sync(qmask, bi2, off);
                if (oz > bv2 || (oz == bv2 && oi < bi2)) { bv2 = oz; bi2 = oi; }
            }
            sec = -3.4e38f;
            #pragma unroll
            for (int k = 0; k < 8; k++) {
                int n = nb + (k >> 1) * 8 + (k & 1);
                if (n != bi2) sec = fmaxf(sec, z[k]);
            }
            sec = fmaxf(sec, __shfl_xor_sync(qmask, sec, 1));
            sec = fmaxf(sec, __shfl_xor_sync(qmask, sec, 2));
            const float m2 = bv2 - sec;

            // Near-tie refinement (quad-uniform condition): recompute this
            // lane's 8 columns with the exact sequential-fmaf fp32 chain
            // (k ascending) — bit-identical to reference numerics.
            if (m1 < REFINE_THR || m2 < REFINE_THR) {
                float ex[8];
                const float4* x4 = (const float4*)(x + (size_t)row * E_);
                #pragma unroll
                for (int kk = 0; kk < 8; kk++) {
                    const int cls = nb + (kk >> 1) * 8 + (kk & 1);
                    const float4* w4 = (const float4*)(W1 + (size_t)cls * E_);
                    float a = 0.f;
                    #pragma unroll 4
                    for (int k = 0; k < E_ / 4; k++) {
                        float4 av = __ldg(&x4[k]);
                        float4 bw = __ldg(&w4[k]);
                        a = fmaf(av.x, bw.x, a);
                        a = fmaf(av.y, bw.y, a);
                        a = fmaf(av.z, bw.z, a);
                        a = fmaf(av.w, bw.w, a);
                    }
                    float cb = fmaf(3.0f, __ldg(&b1[cls]), __ldg(&coff[cls]));
                    ex[kk] = fmaf(3.0f, a, cb);
                }
                // redo draw 1 exactly
                #pragma unroll
                for (int jj = 0; jj < 4; jj++) {
                    float2 ga = __ldg((const float2*)&g1[rowC + nb + jj * 8]);
                    z[jj * 2] = ex[jj * 2] + ga.x; z[jj * 2 + 1] = ex[jj * 2 + 1] + ga.y;
                }
                bv1 = z[0]; bi1 = nb;
                #pragma unroll
                for (int k = 1; k < 8; k++) {
                    int n = nb + (k >> 1) * 8 + (k & 1);
                    if (z[k] > bv1) { bv1 = z[k]; bi1 = n; }
                }
                #pragma unroll
                for (int off = 1; off <= 2; off <<= 1) {
                    float oz = __shfl_xor_sync(qmask, bv1, off);
                    int   oi = __shfl_xor_sync(qmask, bi1, off);
                    if (oz > bv1 || (oz == bv1 && oi < bi1)) { bv1 = oz; bi1 = oi; }
                }
                // redo draw 2 exactly
                #pragma unroll
                for (int jj = 0; jj < 4; jj++) {
                    float2 gb = __ldg((const float2*)&g2[rowC + nb + jj * 8]);
                    z[jj * 2] = ex[jj * 2] + gb.x; z[jj * 2 + 1] = ex[jj * 2 + 1] + gb.y;
                }
                bv2 = z[0]; bi2 = nb;
                #pragma unroll
                for (int k = 1; k < 8; k++) {
                    int n = nb + (k >> 1) * 8 + (k & 1);
                    if (z[k] > bv2) { bv2 = z[k]; bi2 = n; }
                }
                #pragma unroll
                for (int off = 1; off <= 2; off <<= 1) {
                    float oz = __shfl_xor_sync(qmask, bv2, off);
                    int   oi = __shfl_xor_sync(qmask, bi2, off);
                    if (oz > bv2 || (oz == bv2 && oi < bi2)) { bv2 = oz; bi2 = oi; }
                }
            }

            // interpolation weights
            const float wv = __ldg(&wI[row * G_ + gidx]);
            const float uv = __ldg(&uI[row * G_ + gidx]);
            const float cwi = (uv < 1.0f) ? wv : 1.0f;
            const float cwj = (uv < 1.0f) ? (1.0f - wv) : 0.0f;

            // emit soft, sampled (fp32 + fp16)
            #pragma unroll
            for (int jj = 0; jj < 4; jj++) {
                const int n = nb + jj * 8;
                float2 sm, sp;
                sm.x = e[jj * 2] * inv_s;  sm.y = e[jj * 2 + 1] * inv_s;
                sp.x = ((n     == bi1) ? cwi : 0.f) + ((n     == bi2) ? cwj : 0.f);
                sp.y = ((n + 1 == bi1) ? cwi : 0.f) + ((n + 1 == bi2) ? cwj : 0.f);
                *(float2*)&oSoft[rowC + n] = sm;
                *(float2*)&oSamp[rowC + n] = sp;
                ((__half2*)&g_sampH[rowC + n])[0] = __floats2half2_rn(sp.x, sp.y);
            }
        }
    }
}

// ---------------- kernel 3: fp16 GEMM  posPre = sampH @ W2h^T + b2 ---------
__global__ void __launch_bounds__(256, 2)
gemm2_mma(const float* __restrict__ b2)
{
    __shared__ __align__(16) __half sA[2][BM * ASTRIDE];
    __shared__ __align__(16) __half sB[2][BN * ASTRIDE];

    const int tid  = threadIdx.x;
    const int lane = tid & 31;
    const int wid  = tid >> 5;
    const int wm   = (wid & 3) * 32;
    const int wn   = (wid >> 2) * 64;
    const int m0   = blockIdx.y * BM;
    const int n0   = blockIdx.x * BN;

    const uint32_t aBase[2] = { smem_u32(&sA[0][0]), smem_u32(&sA[1][0]) };
    const uint32_t bBase[2] = { smem_u32(&sB[0][0]), smem_u32(&sB[1][0]) };

    const int lrow0 = tid >> 2,         lcg0 = (tid & 3);
    const int lrow1 = (tid + 256) >> 2, lcg1 = ((tid + 256) & 3);

    auto issue_loads = [&](int kc) {
        const int b    = kc & 1;
        const int kcol = kc * BK;
        cp16(aBase[b] + (uint32_t)(lrow0 * ASTRIDE + lcg0 * 8) * 2,
             g_sampH + (size_t)(m0 + lrow0) * C_ + kcol + lcg0 * 8);
        cp16(aBase[b] + (uint32_t)(lrow1 * ASTRIDE + lcg1 * 8) * 2,
             g_sampH + (size_t)(m0 + lrow1) * C_ + kcol + lcg1 * 8);
        cp16(bBase[b] + (uint32_t)(lrow0 * ASTRIDE + lcg0 * 8) * 2,
             g_W2h + (size_t)(n0 + lrow0) * C_ + kcol + lcg0 * 8);
        cp16(bBase[b] + (uint32_t)(lrow1 * ASTRIDE + lcg1 * 8) * 2,
             g_W2h + (size_t)(n0 + lrow1) * C_ + kcol + lcg1 * 8);
        asm volatile("cp.async.commit_group;" ::: "memory");
    };

    float acc[2][8][4];
    #pragma unroll
    for (int i = 0; i < 2; i++)
        #pragma unroll
        for (int j = 0; j < 8; j++)
            #pragma unroll
            for (int r = 0; r < 4; r++) acc[i][j][r] = 0.0f;

    issue_loads(0);

    for (int kc = 0; kc < NCHUNK2; kc++) {
        const int b = kc & 1;
        if (kc + 1 < NCHUNK2) {
            issue_loads(kc + 1);
            asm volatile("cp.async.wait_group 1;" ::: "memory");
        } else {
            asm volatile("cp.async.wait_group 0;" ::: "memory");
        }
        __syncthreads();

        #pragma unroll
        for (int ks = 0; ks < 2; ks++) {
            uint32_t afr[2][4];
            #pragma unroll
            for (int i = 0; i < 2; i++) {
                int row  = wm + i * 16 + (lane & 7) + ((lane >> 3) & 1) * 8;
                int half = lane >> 4;
                ldm_x4(afr[i], aBase[b] + row * (ASTRIDE * 2) + ks * 32 + half * 16);
            }
            uint32_t bfr[8][2];
            #pragma unroll
            for (int bj = 0; bj < 4; bj++) {
                int row  = wn + bj * 16 + (lane & 7) + (lane >> 4) * 8;
                int half = (lane >> 3) & 1;
                uint32_t q[4];
                ldm_x4(q, bBase[b] + row * (ASTRIDE * 2) + ks * 32 + half * 16);
                bfr[bj * 2][0] = q[0];     bfr[bj * 2][1] = q[1];
                bfr[bj * 2 + 1][0] = q[2]; bfr[bj * 2 + 1][1] = q[3];
            }
            #pragma unroll
            for (int i = 0; i < 2; i++)
                #pragma unroll
                for (int j = 0; j < 8; j++)
                    mma16816(acc[i][j], afr[i], bfr[j]);
        }
        __syncthreads();
    }

    const int gp   = lane >> 2;
    const int tid4 = lane & 3;
    #pragma unroll
    for (int j = 0; j < 8; j++) {
        const int n = n0 + wn + j * 8 + tid4 * 2;
        const float c0 = __ldg(&b2[n + 0]);
        const float c1 = __ldg(&b2[n + 1]);
        #pragma unroll
        for (int i = 0; i < 2; i++) {
            const int mrow = m0 + wm + i * 16 + gp;
            float2 v0, v1;
            v0.x = acc[i][j][0] + c0;
            v0.y = acc[i][j][1] + c1;
            v1.x = acc[i][j][2] + c0;
            v1.y = acc[i][j][3] + c1;
            *(float2*)&g_posPre[(size_t)mrow * E_ + n]       = v0;
            *(float2*)&g_posPre[(size_t)(mrow + 8) * E_ + n] = v1;
        }
    }
}

// ---------------- kernel 4: LayerNorm over posPre -> oPos, oNeg ------------
__global__ void __launch_bounds__(256)
ln_k(const float* __restrict__ gamma, const float* __restrict__ beta,
     float* __restrict__ oPos, float* __restrict__ oNeg)
{
    const int t    = blockIdx.x;
    const int tid  = threadIdx.x;
    const int lane = tid & 31;
    const int wid  = tid >> 5;
    __shared__ float rbuf[18];

    float2 v = ((const float2*)g_posPre)[(size_t)t * 256 + tid];

    float s_sum = v.x + v.y;
    float s_sq  = v.x * v.x + v.y * v.y;
    #pragma unroll
    for (int off = 16; off; off >>= 1) {
        s_sum += __shfl_xor_sync(0xffffffffu, s_sum, off);
        s_sq  += __shfl_xor_sync(0xffffffffu, s_sq,  off);
    }
    if (lane == 0) { rbuf[wid] = s_sum; rbuf[8 + wid] = s_sq; }
    __syncthreads();
    if (tid == 0) {
        float S = 0.f, S2 = 0.f;
        #pragma unroll
        for (int w = 0; w < 8; w++) { S += rbuf[w]; S2 += rbuf[8 + w]; }
        float mu  = S * (1.0f / E_);
        float var = S2 * (1.0f / E_) - mu * mu;
        rbuf[16] = mu;
        rbuf[17] = rsqrtf(var + LN_EPS);
    }
    __syncthreads();
    const float mu = rbuf[16], inv = rbuf[17];

    float2 gm = __ldg(&((const float2*)gamma)[tid]);
    float2 bt = __ldg(&((const float2*)beta)[tid]);
    float2 y;
    y.x = (v.x - mu) * inv * gm.x + bt.x;
    y.y = (v.y - mu) * inv * gm.y + bt.y;
    const size_t baseE2 = (size_t)t * 256;
    ((float2*)oPos)[baseE2 + tid] = y;
    ((float2*)oNeg)[baseE2 + tid] = y;
}

// ---------------- launcher (pure kernel launches; graph-capture safe) ------
extern "C" void kernel_launch(void* const* d_in, const int* in_sizes, int n_in,
                              void* d_out, int out_size)
{
    const float* x     = (const float*)d_in[0];
    const float* W1    = (const float*)d_in[1];
    const float* b1    = (const float*)d_in[2];
    const float* coff  = (const float*)d_in[3];
    const float* W2    = (const float*)d_in[4];
    const float* b2    = (const float*)d_in[5];
    const float* gam   = (const float*)d_in[6];
    const float* bet   = (const float*)d_in[7];
    const float* g1    = (const float*)d_in[8];
    const float* g2    = (const float*)d_in[9];
    const float* wI    = (const float*)d_in[10];
    const float* uI    = (const float*)d_in[11];

    float* out     = (float*)d_out;
    float* o_samp  = out;
    float* o_soft  = out + (size_t)TOK_ * C_;
    float* o_pos   = out + (size_t)2 * TOK_ * C_;
    float* o_neg   = o_pos + (size_t)TOK_ * E_;

    split_x_k<<<(TOK_ * E_ / 4 + 255) / 256, 256>>>(x);
    split_w_k<<<(C_ * E_ / 4 + 255) / 256, 256>>>(W1);
    w2h_k<<<(E_ * C_ / 4 + 255) / 256, 256>>>(W2);
    gemm_mma<<<dim3(C_ / BN, TOK_ / BM), 256>>>(b1, coff, x, W1,
                                                g1, g2, wI, uI,
                                                o_samp, o_soft);
    gemm2_mma<<<dim3(E_ / BN, TOK_ / BM), 256>>>(b2);
    ln_k<<<TOK_, 256>>>(gam, bet, o_pos, o_neg);
}

// round 14
// speedup vs baseline: 2.1524x; 2.1524x over previous
#include <cuda_runtime.h>
#include <cuda_fp16.h>
#include <cstdint>

// ---------------- problem constants ----------------
#define S_    2048
#define N_    8
#define E_    512
#define C_    1024
#define G_    32
#define CG_   32
#define TOK_  (S_ * N_)          // 16384 tokens
#define LN_EPS 1e-5f

// GEMM tiling (mma.sync path — tcgen05 unavailable on this toolchain)
#define BM 128
#define BN 128
#define BK 32
#define NCHUNK1 32                // gemm1: 2 fp16 split segments x (512/32)
#define NCHUNK2 32                // gemm2: K=1024 / 32
#define ASTRIDE 40                // smem row stride in fp16 elems (80 B)

// refinement trigger: fp16-2seg logit error bound ~8e-4 max; 5x headroom
#define REFINE_THR 4e-3f

// ---------------- scratch (device globals) --------
__device__ float  g_logits[(size_t)TOK_ * C_];         // 64 MB
__device__ __half g_Ahi[(size_t)TOK_ * E_];            // 16 MB
__device__ __half g_Alo[(size_t)TOK_ * E_];            // 16 MB
__device__ __half g_Bhi[(size_t)C_ * E_];              // 1 MB
__device__ __half g_sampH[(size_t)TOK_ * C_];          // 32 MB (fp16 sampled)
__device__ __half g_W2h[(size_t)E_ * C_];              // 1 MB  (fp16 W2, [e][c])
__device__ float  g_posPre[(size_t)TOK_ * E_];         // 32 MB (pre-LN projection)

// ---------------- helpers ----------------
__device__ __forceinline__ uint32_t smem_u32(const void* p) {
    uint32_t a;
    asm("{ .reg .u64 t; cvta.to.shared.u64 t, %1; cvt.u32.u64 %0, t; }"
        : "=r"(a) : "l"(p));
    return a;
}
__device__ __forceinline__ void cp16(uint32_t saddr, const void* gptr) {
    asm volatile("cp.async.cg.shared.global [%0], [%1], 16;"
                 :: "r"(saddr), "l"(gptr) : "memory");
}
__device__ __forceinline__ void ldm_x4(uint32_t* r, uint32_t addr) {
    asm volatile("ldmatrix.sync.aligned.m8n8.x4.shared.b16 {%0,%1,%2,%3}, [%4];"
                 : "=r"(r[0]), "=r"(r[1]), "=r"(r[2]), "=r"(r[3]) : "r"(addr));
}
__device__ __forceinline__ void mma16816(float* c, const uint32_t* a, const uint32_t* b) {
    asm volatile(
        "mma.sync.aligned.m16n8k16.row.col.f32.f16.f16.f32 "
        "{%0,%1,%2,%3}, {%4,%5,%6,%7}, {%8,%9}, {%0,%1,%2,%3};"
        : "+f"(c[0]), "+f"(c[1]), "+f"(c[2]), "+f"(c[3])
        : "r"(a[0]), "r"(a[1]), "r"(a[2]), "r"(a[3]), "r"(b[0]), "r"(b[1]));
}
// order-preserving float->u32 key (exact, monotone)
__device__ __forceinline__ uint32_t fkey(float f) {
    uint32_t b = __float_as_uint(f);
    return (b & 0x80000000u) ? ~b : (b | 0x80000000u);
}
__device__ __forceinline__ float funkey(uint32_t k) {
    uint32_t b = (k & 0x80000000u) ? (k & 0x7fffffffu) : ~k;
    return __uint_as_float(b);
}
__device__ __forceinline__ uint32_t redux_max_u32(uint32_t v) {
    uint32_t r;
    asm volatile("redux.sync.max.u32 %0, %1, 0xffffffff;" : "=r"(r) : "r"(v));
    return r;
}

// ---------------- kernel 0a: fp32 -> (fp16 hi, fp16 lo) split of x --------
__global__ void split_x_k(const float* __restrict__ in) {
    int i = blockIdx.x * 256 + threadIdx.x;
    if (i < TOK_ * E_ / 4) {
        float4 v = ((const float4*)in)[i];
        __half h0 = __float2half_rn(v.x), h1 = __float2half_rn(v.y);
        __half h2 = __float2half_rn(v.z), h3 = __float2half_rn(v.w);
        __half2 hi01, hi23, lo01, lo23;
        hi01.x = h0; hi01.y = h1; hi23.x = h2; hi23.y = h3;
        lo01.x = __float2half_rn(v.x - __half2float(h0));
        lo01.y = __float2half_rn(v.y - __half2float(h1));
        lo23.x = __float2half_rn(v.z - __half2float(h2));
        lo23.y = __float2half_rn(v.w - __half2float(h3));
        ((__half2*)g_Ahi)[i * 2]     = hi01;
        ((__half2*)g_Ahi)[i * 2 + 1] = hi23;
        ((__half2*)g_Alo)[i * 2]     = lo01;
        ((__half2*)g_Alo)[i * 2 + 1] = lo23;
    }
}
// ---------------- kernel 0b: W1 -> fp16 ------------------------------------
__global__ void split_w_k(const float* __restrict__ in) {
    int i = blockIdx.x * 256 + threadIdx.x;
    if (i < C_ * E_ / 4) {
        float4 v = ((const float4*)in)[i];
        __half2 hi01, hi23;
        hi01.x = __float2half_rn(v.x); hi01.y = __float2half_rn(v.y);
        hi23.x = __float2half_rn(v.z); hi23.y = __float2half_rn(v.w);
        ((__half2*)g_Bhi)[i * 2]     = hi01;
        ((__half2*)g_Bhi)[i * 2 + 1] = hi23;
    }
}
// ---------------- kernel 0c: W2 -> fp16 (layout kept: [e][c]) --------------
__global__ void w2h_k(const float* __restrict__ in) {
    int i = blockIdx.x * 256 + threadIdx.x;
    if (i < E_ * C_ / 4) {
        float4 v = ((const float4*)in)[i];
        __half2 h01, h23;
        h01.x = __float2half_rn(v.x); h01.y = __float2half_rn(v.y);
        h23.x = __float2half_rn(v.z); h23.y = __float2half_rn(v.w);
        ((__half2*)g_W2h)[i * 2]     = h01;
        ((__half2*)g_W2h)[i * 2 + 1] = h23;
    }
}

// ---------------- kernel 1: fp16 split-GEMM  logits = 3(xW1^T + b1) + coff -
// (proven 123us version — skinny epilogue, NO fusion)
__global__ void __launch_bounds__(256, 2)
gemm_mma(const float* __restrict__ b1, const float* __restrict__ coff)
{
    __shared__ __align__(16) __half sA[2][BM * ASTRIDE];
    __shared__ __align__(16) __half sB[2][BN * ASTRIDE];

    const int tid  = threadIdx.x;
    const int lane = tid & 31;
    const int wid  = tid >> 5;
    const int wm   = (wid & 3) * 32;
    const int wn   = (wid >> 2) * 64;
    const int m0   = blockIdx.y * BM;
    const int n0   = blockIdx.x * BN;

    const uint32_t aBase[2] = { smem_u32(&sA[0][0]), smem_u32(&sA[1][0]) };
    const uint32_t bBase[2] = { smem_u32(&sB[0][0]), smem_u32(&sB[1][0]) };

    const int lrow0 = tid >> 2,         lcg0 = (tid & 3);
    const int lrow1 = (tid + 256) >> 2, lcg1 = ((tid + 256) & 3);

    auto issue_loads = [&](int kc) {
        const int b   = kc & 1;
        const int seg = kc >> 4;
        const __half* Asrc = seg ? g_Alo : g_Ahi;
        const int kcol = (kc & 15) * BK;
        cp16(aBase[b] + (uint32_t)(lrow0 * ASTRIDE + lcg0 * 8) * 2,
             Asrc + (size_t)(m0 + lrow0) * E_ + kcol + lcg0 * 8);
        cp16(aBase[b] + (uint32_t)(lrow1 * ASTRIDE + lcg1 * 8) * 2,
             Asrc + (size_t)(m0 + lrow1) * E_ + kcol + lcg1 * 8);
        cp16(bBase[b] + (uint32_t)(lrow0 * ASTRIDE + lcg0 * 8) * 2,
             g_Bhi + (size_t)(n0 + lrow0) * E_ + kcol + lcg0 * 8);
        cp16(bBase[b] + (uint32_t)(lrow1 * ASTRIDE + lcg1 * 8) * 2,
             g_Bhi + (size_t)(n0 + lrow1) * E_ + kcol + lcg1 * 8);
        asm volatile("cp.async.commit_group;" ::: "memory");
    };

    float acc[2][8][4];
    #pragma unroll
    for (int i = 0; i < 2; i++)
        #pragma unroll
        for (int j = 0; j < 8; j++)
            #pragma unroll
            for (int r = 0; r < 4; r++) acc[i][j][r] = 0.0f;

    issue_loads(0);

    for (int kc = 0; kc < NCHUNK1; kc++) {
        const int b = kc & 1;
        if (kc + 1 < NCHUNK1) {
            issue_loads(kc + 1);
            asm volatile("cp.async.wait_group 1;" ::: "memory");
        } else {
            asm volatile("cp.async.wait_group 0;" ::: "memory");
        }
        __syncthreads();

        #pragma unroll
        for (int ks = 0; ks < 2; ks++) {
            uint32_t afr[2][4];
            #pragma unroll
            for (int i = 0; i < 2; i++) {
                int row  = wm + i * 16 + (lane & 7) + ((lane >> 3) & 1) * 8;
                int half = lane >> 4;
                ldm_x4(afr[i], aBase[b] + row * (ASTRIDE * 2) + ks * 32 + half * 16);
            }
            uint32_t bfr[8][2];
            #pragma unroll
            for (int bj = 0; bj < 4; bj++) {
                int row  = wn + bj * 16 + (lane & 7) + (lane >> 4) * 8;
                int half = (lane >> 3) & 1;
                uint32_t q[4];
                ldm_x4(q, bBase[b] + row * (ASTRIDE * 2) + ks * 32 + half * 16);
                bfr[bj * 2][0] = q[0];     bfr[bj * 2][1] = q[1];
                bfr[bj * 2 + 1][0] = q[2]; bfr[bj * 2 + 1][1] = q[3];
            }
            #pragma unroll
            for (int i = 0; i < 2; i++)
                #pragma unroll
                for (int j = 0; j < 8; j++)
                    mma16816(acc[i][j], afr[i], bfr[j]);
        }
        __syncthreads();
    }

    const int gp   = lane >> 2;
    const int tid4 = lane & 3;
    #pragma unroll
    for (int j = 0; j < 8; j++) {
        const int n = n0 + wn + j * 8 + tid4 * 2;
        const float c0 = fmaf(3.0f, __ldg(&b1[n + 0]), __ldg(&coff[n + 0]));
        const float c1 = fmaf(3.0f, __ldg(&b1[n + 1]), __ldg(&coff[n + 1]));
        #pragma unroll
        for (int i = 0; i < 2; i++) {
            const int mrow = m0 + wm + i * 16 + gp;
            float2 v0, v1;
            v0.x = fmaf(3.0f, acc[i][j][0], c0);
            v0.y = fmaf(3.0f, acc[i][j][1], c1);
            v1.x = fmaf(3.0f, acc[i][j][2], c0);
            v1.y = fmaf(3.0f, acc[i][j][3], c1);
            *(float2*)&g_logits[(size_t)mrow * C_ + n]       = v0;
            *(float2*)&g_logits[(size_t)(mrow + 8) * C_ + n] = v1;
        }
    }
}

// ---------------- kernel 3: fp16 GEMM  posPre = sampH @ W2h^T + b2 ---------
__global__ void __launch_bounds__(256, 2)
gemm2_mma(const float* __restrict__ b2)
{
    __shared__ __align__(16) __half sA[2][BM * ASTRIDE];
    __shared__ __align__(16) __half sB[2][BN * ASTRIDE];

    const int tid  = threadIdx.x;
    const int lane = tid & 31;
    const int wid  = tid >> 5;
    const int wm   = (wid & 3) * 32;
    const int wn   = (wid >> 2) * 64;
    const int m0   = blockIdx.y * BM;
    const int n0   = blockIdx.x * BN;

    const uint32_t aBase[2] = { smem_u32(&sA[0][0]), smem_u32(&sA[1][0]) };
    const uint32_t bBase[2] = { smem_u32(&sB[0][0]), smem_u32(&sB[1][0]) };

    const int lrow0 = tid >> 2,         lcg0 = (tid & 3);
    const int lrow1 = (tid + 256) >> 2, lcg1 = ((tid + 256) & 3);

    auto issue_loads = [&](int kc) {
        const int b    = kc & 1;
        const int kcol = kc * BK;
        cp16(aBase[b] + (uint32_t)(lrow0 * ASTRIDE + lcg0 * 8) * 2,
             g_sampH + (size_t)(m0 + lrow0) * C_ + kcol + lcg0 * 8);
        cp16(aBase[b] + (uint32_t)(lrow1 * ASTRIDE + lcg1 * 8) * 2,
             g_sampH + (size_t)(m0 + lrow1) * C_ + kcol + lcg1 * 8);
        cp16(bBase[b] + (uint32_t)(lrow0 * ASTRIDE + lcg0 * 8) * 2,
             g_W2h + (size_t)(n0 + lrow0) * C_ + kcol + lcg0 * 8);
        cp16(bBase[b] + (uint32_t)(lrow1 * ASTRIDE + lcg1 * 8) * 2,
             g_W2h + (size_t)(n0 + lrow1) * C_ + kcol + lcg1 * 8);
        asm volatile("cp.async.commit_group;" ::: "memory");
    };

    float acc[2][8][4];
    #pragma unroll
    for (int i = 0; i < 2; i++)
        #pragma unroll
        for (int j = 0; j < 8; j++)
            #pragma unroll
            for (int r = 0; r < 4; r++) acc[i][j][r] = 0.0f;

    issue_loads(0);

    for (int kc = 0; kc < NCHUNK2; kc++) {
        const int b = kc & 1;
        if (kc + 1 < NCHUNK2) {
            issue_loads(kc + 1);
            asm volatile("cp.async.wait_group 1;" ::: "memory");
        } else {
            asm volatile("cp.async.wait_group 0;" ::: "memory");
        }
        __syncthreads();

        #pragma unroll
        for (int ks = 0; ks < 2; ks++) {
            uint32_t afr[2][4];
            #pragma unroll
            for (int i = 0; i < 2; i++) {
                int row  = wm + i * 16 + (lane & 7) + ((lane >> 3) & 1) * 8;
                int half = lane >> 4;
                ldm_x4(afr[i], aBase[b] + row * (ASTRIDE * 2) + ks * 32 + half * 16);
            }
            uint32_t bfr[8][2];
            #pragma unroll
            for (int bj = 0; bj < 4; bj++) {
                int row  = wn + bj * 16 + (lane & 7) + (lane >> 4) * 8;
                int half = (lane >> 3) & 1;
                uint32_t q[4];
                ldm_x4(q, bBase[b] + row * (ASTRIDE * 2) + ks * 32 + half * 16);
                bfr[bj * 2][0] = q[0];     bfr[bj * 2][1] = q[1];
                bfr[bj * 2 + 1][0] = q[2]; bfr[bj * 2 + 1][1] = q[3];
            }
            #pragma unroll
            for (int i = 0; i < 2; i++)
                #pragma unroll
                for (int j = 0; j < 8; j++)
                    mma16816(acc[i][j], afr[i], bfr[j]);
        }
        __syncthreads();
    }

    const int gp   = lane >> 2;
    const int tid4 = lane & 3;
    #pragma unroll
    for (int j = 0; j < 8; j++) {
        const int n = n0 + wn + j * 8 + tid4 * 2;
        const float c0 = __ldg(&b2[n + 0]);
        const float c1 = __ldg(&b2[n + 1]);
        #pragma unroll
        for (int i = 0; i < 2; i++) {
            const int mrow = m0 + wm + i * 16 + gp;
            float2 v0, v1;
            v0.x = acc[i][j][0] + c0;
            v0.y = acc[i][j][1] + c1;
            v1.x = acc[i][j][2] + c0;
            v1.y = acc[i][j][3] + c1;
            *(float2*)&g_posPre[(size_t)mrow * E_ + n]       = v0;
            *(float2*)&g_posPre[(size_t)(mrow + 8) * E_ + n] = v1;
        }
    }
}

// ---------------- warp helper (refinement path only) ----------------------
__device__ __forceinline__ int warp_argmax(float z, int lane) {
    float bv = z; int bi = lane;
    #pragma unroll
    for (int off = 16; off; off >>= 1) {
        float ov = __shfl_xor_sync(0xffffffffu, bv, off);
        int   oi = __shfl_xor_sync(0xffffffffu, bi, off);
        if (ov > bv || (ov == bv && oi < bi)) { bv = ov; bi = oi; }
    }
    return bi;
}

// ---------------- kernel 2: softmax + Gumbel sampling per token ------------
// Batched preload (MLP~14) before the latency-bound reduction chains.
__global__ void __launch_bounds__(256)
samp_k(const float* __restrict__ g1, const float* __restrict__ g2,
       const float* __restrict__ wI, const float* __restrict__ uI,
       const float* __restrict__ x,  const float* __restrict__ W1,
       const float* __restrict__ b1, const float* __restrict__ coff,
       float* __restrict__ oSamp, float* __restrict__ oSoft)
{
    const int t    = blockIdx.x;
    const int tid  = threadIdx.x;
    const int lane = tid & 31;
    const int wid  = tid >> 5;

    const size_t baseC = (size_t)t * C_;

    // ---- preload all 4 group-iterations (independent loads, high MLP) ----
    float v[4], a1[4], a2[4], wv[4], uv[4];
    #pragma unroll
    for (int it = 0; it < 4; it++) {
        const int g = wid + it * 8;
        const size_t idx = baseC + g * CG_ + lane;
        v[it]  = g_logits[idx];
        a1[it] = __ldg(&g1[idx]);
        a2[it] = __ldg(&g2[idx]);
        wv[it] = __ldg(&wI[t * G_ + g]);
        uv[it] = __ldg(&uI[t * G_ + g]);
    }

    #pragma unroll
    for (int it = 0; it < 4; it++) {
        const int g = wid + it * 8;
        const size_t idx = baseC + g * CG_ + lane;

        // softmax: exact max via redux on order-preserving key
        float m = funkey(redux_max_u32(fkey(v[it])));
        float e = __expf(v[it] - m);
        float s = e;
        #pragma unroll
        for (int off = 16; off; off >>= 1)
            s += __shfl_xor_sync(0xffffffffu, s, off);
        oSoft[idx] = e / s;

        // argmax + margin via redux/ballot (exact; lowest-index tie)
        float z1 = v[it] + a1[it];
        uint32_t k1 = fkey(z1);
        uint32_t km1 = redux_max_u32(k1);
        int i1 = __ffs(__ballot_sync(0xffffffffu, k1 == km1)) - 1;
        float m1 = funkey(km1) - funkey(redux_max_u32(lane == i1 ? 0u : k1));

        float z2 = v[it] + a2[it];
        uint32_t k2 = fkey(z2);
        uint32_t km2 = redux_max_u32(k2);
        int i2 = __ffs(__ballot_sync(0xffffffffu, k2 == km2)) - 1;
        float m2 = funkey(km2) - funkey(redux_max_u32(lane == i2 ? 0u : k2));

        // Near-tie refinement: exact sequential-fmaf fp32 chain (k ascending),
        // bit-identical to the proven fp32 reference numerics.
        if (m1 < REFINE_THR || m2 < REFINE_THR) {
            const int cls = g * CG_ + lane;
            const float4* x4 = (const float4*)(x + (size_t)t * E_);
            const float4* w4 = (const float4*)(W1 + (size_t)cls * E_);
            float acc = 0.f;
            #pragma unroll 4
            for (int k = 0; k < E_ / 4; k++) {
                float4 a = __ldg(&x4[k]);
                float4 b = __ldg(&w4[k]);
                acc = fmaf(a.x, b.x, acc);
                acc = fmaf(a.y, b.y, acc);
                acc = fmaf(a.z, b.z, acc);
                acc = fmaf(a.w, b.w, acc);
            }
            float cb = fmaf(3.0f, __ldg(&b1[cls]), __ldg(&coff[cls]));
            float vr = fmaf(3.0f, acc, cb);
            i1 = warp_argmax(vr + a1[it], lane);
            i2 = warp_argmax(vr + a2[it], lane);
        }

        float cwi, cwj;
        if (uv[it] < 1.0f) { cwi = wv[it]; cwj = 1.0f - wv[it]; }
        else               { cwi = 1.0f;   cwj = 0.0f;          }

        float val = 0.0f;
        if (lane == i1) val += cwi;
        if (lane == i2) val += cwj;
        oSamp[idx]   = val;
        g_sampH[idx] = __float2half_rn(val);
    }
}

// ---------------- kernel 4: LayerNorm over posPre -> oPos, oNeg ------------
__global__ void __launch_bounds__(256)
ln_k(const float* __restrict__ gamma, const float* __restrict__ beta,
     float* __restrict__ oPos, float* __restrict__ oNeg)
{
    const int t    = blockIdx.x;
    const int tid  = threadIdx.x;
    const int lane = tid & 31;
    const int wid  = tid >> 5;
    __shared__ float rbuf[18];

    float2 v = ((const float2*)g_posPre)[(size_t)t * 256 + tid];

    float s_sum = v.x + v.y;
    float s_sq  = v.x * v.x + v.y * v.y;
    #pragma unroll
    for (int off = 16; off; off >>= 1) {
        s_sum += __shfl_xor_sync(0xffffffffu, s_sum, off);
        s_sq  += __shfl_xor_sync(0xffffffffu, s_sq,  off);
    }
    if (lane == 0) { rbuf[wid] = s_sum; rbuf[8 + wid] = s_sq; }
    __syncthreads();
    if (tid == 0) {
        float S = 0.f, S2 = 0.f;
        #pragma unroll
        for (int w = 0; w < 8; w++) { S += rbuf[w]; S2 += rbuf[8 + w]; }
        float mu  = S * (1.0f / E_);
        float var = S2 * (1.0f / E_) - mu * mu;
        rbuf[16] = mu;
        rbuf[17] = rsqrtf(var + LN_EPS);
    }
    __syncthreads();
    const float mu = rbuf[16], inv = rbuf[17];

    float2 gm = __ldg(&((const float2*)gamma)[tid]);
    float2 bt = __ldg(&((const float2*)beta)[tid]);
    float2 y;
    y.x = (v.x - mu) * inv * gm.x + bt.x;
    y.y = (v.y - mu) * inv * gm.y + bt.y;
    const size_t baseE2 = (size_t)t * 256;
    ((float2*)oPos)[baseE2 + tid] = y;
    ((float2*)oNeg)[baseE2 + tid] = y;
}

// ---------------- launcher (pure kernel launches; graph-capture safe) ------
extern "C" void kernel_launch(void* const* d_in, const int* in_sizes, int n_in,
                              void* d_out, int out_size)
{
    const float* x     = (const float*)d_in[0];
    const float* W1    = (const float*)d_in[1];
    const float* b1    = (const float*)d_in[2];
    const float* coff  = (const float*)d_in[3];
    const float* W2    = (const float*)d_in[4];
    const float* b2    = (const float*)d_in[5];
    const float* gam   = (const float*)d_in[6];
    const float* bet   = (const float*)d_in[7];
    const float* g1    = (const float*)d_in[8];
    const float* g2    = (const float*)d_in[9];
    const float* wI    = (const float*)d_in[10];
    const float* uI    = (const float*)d_in[11];

    float* out     = (float*)d_out;
    float* o_samp  = out;
    float* o_soft  = out + (size_t)TOK_ * C_;
    float* o_pos   = out + (size_t)2 * TOK_ * C_;
    float* o_neg   = o_pos + (size_t)TOK_ * E_;

    split_x_k<<<(TOK_ * E_ / 4 + 255) / 256, 256>>>(x);
    split_w_k<<<(C_ * E_ / 4 + 255) / 256, 256>>>(W1);
    w2h_k<<<(E_ * C_ / 4 + 255) / 256, 256>>>(W2);
    gemm_mma<<<dim3(C_ / BN, TOK_ / BM), 256>>>(b1, coff);
    samp_k<<<TOK_, 256>>>(g1, g2, wI, uI, x, W1, b1, coff, o_samp, o_soft);
    gemm2_mma<<<dim3(E_ / BN, TOK_ / BM), 256>>>(b2);
    ln_k<<<TOK_, 256>>>(gam, bet, o_pos, o_neg);
}